// round 10
// baseline (speedup 1.0000x reference)
#include <cuda_runtime.h>
#include <cstdint>

#define N_VOX   262144
#define M_PAIRS 131072
#define K_OFF   27
#define C       32
#define CPAD    36        // row stride in floats (144B)

// ---------------------------------------------------------------------------
// Kernel 1: out[n][c] = bias[c]  (bias add commutes with the scatter-adds)
// ---------------------------------------------------------------------------
__global__ void bias_init_kernel(float* __restrict__ out,
                                 const float* __restrict__ bias)
{
    int t = blockIdx.x * blockDim.x + threadIdx.x;
    const int total4 = N_VOX * (C / 4);
    if (t < total4) {
        const float4* b4 = (const float4*)bias;
        float4* o4 = (float4*)out;
        o4[t] = b4[t & 7];
    }
}

// ---------------------------------------------------------------------------
// Kernel 2: staged gather -> smem -> split-K f32x2 GEMM -> red.v2.
//
//   One pair per warp-step. lane&15 = channel pair (2c, 2c+1); lane>>4 picks
//   the INPUT half (0: inputs 0-15, 1: inputs 16-31). Each lane holds only
//   its half's weights (16 b64 = 32 regs, no duplication -> higher occ).
//   Halves combined via 64-bit shfl.xor(16) + packed f32x2 adds; lanes<16
//   issue the contiguous red.v2 scatter.
// ---------------------------------------------------------------------------
#define THREADS          128
#define WARPS_PER_BLOCK  4
#define PAIRS_PER_BLOCK  128
#define PAIRS_PER_WARP   32

__global__ __launch_bounds__(THREADS, 7)
void scatter_gemm_kernel(const float* __restrict__ input,
                         const float* __restrict__ kernel,
                         const int*   __restrict__ in_map,
                         const int*   __restrict__ out_map,
                         float*       __restrict__ out)
{
    __shared__ float srow[PAIRS_PER_BLOCK][CPAD];    // 18 KB staged rows

    const int k     = blockIdx.y;
    const int lane  = threadIdx.x & 31;
    const int warp  = threadIdx.x >> 5;
    const int half  = lane >> 4;          // input half: 0 -> in[0..15], 1 -> in[16..31]
    const int chalf = lane & 15;          // covers channels 2*chalf, 2*chalf+1

    const int tile = blockIdx.x * PAIRS_PER_BLOCK;
    const int* im  = in_map  + k * M_PAIRS + tile;
    const int* om  = out_map + k * M_PAIRS + tile;

    // ---- Stage: 128 rows x 8 quads, coalesced; 8 float4 per thread.
    #pragma unroll
    for (int i = 0; i < (PAIRS_PER_BLOCK * (C / 4)) / THREADS; i++) {
        int q  = threadIdx.x + i * THREADS;
        int pr = q >> 3;
        int qq = q & 7;
        int irow = __ldg(im + pr);
        ((float4*)&srow[pr][0])[qq] =
            __ldg((const float4*)(input + (size_t)irow * C) + qq);
    }

    // ---- Weights for THIS half's 16 inputs only, input-pair packed:
    //   wA[i] = (W[base+2i][c0], W[base+2i+1][c0]),  wB likewise for c1.
    const float* Wk    = kernel + k * C * C;
    const int    ibase = half * 16;
    unsigned long long wA[8], wB[8];
    #pragma unroll
    for (int i = 0; i < 8; i++) {
        float2 f = __ldg((const float2*)(Wk + (ibase + 2 * i)     * C) + chalf);
        float2 g = __ldg((const float2*)(Wk + (ibase + 2 * i + 1) * C) + chalf);
        asm("mov.b64 %0, {%1, %2};" : "=l"(wA[i]) : "f"(f.x), "f"(g.x));
        asm("mov.b64 %0, {%1, %2};" : "=l"(wB[i]) : "f"(f.y), "f"(g.y));
    }

    __syncthreads();

    const int pbase = warp * PAIRS_PER_WARP;

    #pragma unroll 4
    for (int p = 0; p < PAIRS_PER_WARP; p++) {
        const int pr   = pbase + p;
        const int orow = __ldg(om + pr);        // warp-uniform load

        // This half's 64B of the row: 16B chunks [half*4 .. half*4+3].
        const ulonglong2* r2 =
            (const ulonglong2*)((const char*)&srow[pr][0] + half * 64);

        unsigned long long accA = 0ULL, accB = 0ULL;   // packed (even, odd) partials
        #pragma unroll
        for (int j = 0; j < 4; j++) {
            ulonglong2 a = r2[j];               // LDS.128, 2 distinct addrs per warp
            asm("fma.rn.f32x2 %0, %1, %2, %0;" : "+l"(accA) : "l"(a.x), "l"(wA[2 * j]));
            asm("fma.rn.f32x2 %0, %1, %2, %0;" : "+l"(accA) : "l"(a.y), "l"(wA[2 * j + 1]));
            asm("fma.rn.f32x2 %0, %1, %2, %0;" : "+l"(accB) : "l"(a.x), "l"(wB[2 * j]));
            asm("fma.rn.f32x2 %0, %1, %2, %0;" : "+l"(accB) : "l"(a.y), "l"(wB[2 * j + 1]));
        }

        // Combine input-halves: 64-bit shfl.xor(16) + packed adds.
        unsigned long long rA = __shfl_xor_sync(0xffffffffu, accA, 16);
        unsigned long long rB = __shfl_xor_sync(0xffffffffu, accB, 16);
        asm("add.rn.f32x2 %0, %0, %1;" : "+l"(accA) : "l"(rA));
        asm("add.rn.f32x2 %0, %0, %1;" : "+l"(accB) : "l"(rB));

        float a0, a1, b0, b1;
        asm("mov.b64 {%0, %1}, %2;" : "=f"(a0), "=f"(a1) : "l"(accA));
        asm("mov.b64 {%0, %1}, %2;" : "=f"(b0), "=f"(b1) : "l"(accB));
        const float c0 = a0 + a1;
        const float c1 = b0 + b1;

        if (half == 0) {
            float* dst = out + (size_t)orow * C + 2 * chalf;   // 8B aligned
            asm volatile("red.global.add.v2.f32 [%0], {%1, %2};"
                         :: "l"(dst), "f"(c0), "f"(c1) : "memory");
        }
    }
}

// ---------------------------------------------------------------------------
// Launch
// ---------------------------------------------------------------------------
extern "C" void kernel_launch(void* const* d_in, const int* in_sizes, int n_in,
                              void* d_out, int out_size)
{
    const float* input   = (const float*)d_in[0];
    const float* kernelw = (const float*)d_in[1];
    const float* bias    = (const float*)d_in[2];
    const int*   in_map  = (const int*)  d_in[3];
    const int*   out_map = (const int*)  d_in[4];
    float*       out     = (float*)d_out;

    const int total4 = N_VOX * (C / 4);
    bias_init_kernel<<<(total4 + 255) / 256, 256>>>(out, bias);

    dim3 grid(M_PAIRS / PAIRS_PER_BLOCK, K_OFF);
    scatter_gemm_kernel<<<grid, THREADS>>>(input, kernelw, in_map, out_map, out);
}

// round 11
// speedup vs baseline: 1.0790x; 1.0790x over previous
#include <cuda_runtime.h>
#include <cstdint>

#define N_VOX   262144
#define M_PAIRS 131072
#define K_OFF   27
#define C       32
#define CPAD    36        // row stride in floats (144B)

// ---------------------------------------------------------------------------
// Kernel 1: out[n][c] = bias[c]  (bias add commutes with the scatter-adds)
// ---------------------------------------------------------------------------
__global__ void bias_init_kernel(float* __restrict__ out,
                                 const float* __restrict__ bias)
{
    int t = blockIdx.x * blockDim.x + threadIdx.x;
    const int total4 = N_VOX * (C / 4);
    if (t < total4) {
        const float4* b4 = (const float4*)bias;
        float4* o4 = (float4*)out;
        o4[t] = b4[t & 7];
    }
}

// ---------------------------------------------------------------------------
// Kernel 2: staged gather -> smem -> input-packed f32x2 GEMM (R9 scheme)
//           -> smem result buffer -> TMA bulk-reduction scatter.
//
//   Compute (R9, best known): 16-lane half-warp owns one pair; lane covers
//   channels (2c, 2c+1); input read as ulonglong2 (LDS.128 -> packed f32x2
//   pairs) consumed directly by fma.rn.f32x2; no movs, no shfl.
//   Scatter: results staged to a per-warp smem buffer (STS.64), then
//   cp.reduce.async.bulk.global...add.f32 (128B per pair) issued from
//   lanes 0-3. Reduction happens in the TMA/L2 path -> zero L1 RED slots.
// ---------------------------------------------------------------------------
#define THREADS          128
#define WARPS_PER_BLOCK  4
#define PAIRS_PER_BLOCK  128
#define PAIRS_PER_WARP   32
#define STEPS            16            // 2 pairs per step (one per half-warp)

__device__ __forceinline__ uint32_t smem_u32(const void* p) {
    uint32_t a;
    asm("{ .reg .u64 t; cvta.to.shared.u64 t, %1; cvt.u32.u64 %0, t; }"
        : "=r"(a) : "l"(p));
    return a;
}

__global__ __launch_bounds__(THREADS)
void scatter_gemm_kernel(const float* __restrict__ input,
                         const float* __restrict__ kernel,
                         const int*   __restrict__ in_map,
                         const int*   __restrict__ out_map,
                         float*       __restrict__ out)
{
    __shared__ float srow[PAIRS_PER_BLOCK][CPAD];                    // 18 KB
    __shared__ float sres[WARPS_PER_BLOCK][PAIRS_PER_WARP][C];      // 16 KB

    const int k     = blockIdx.y;
    const int lane  = threadIdx.x & 31;
    const int warp  = threadIdx.x >> 5;
    const int half  = lane >> 4;          // which pair of the step
    const int chalf = lane & 15;          // covers channels 2*chalf, 2*chalf+1

    const int tile = blockIdx.x * PAIRS_PER_BLOCK;
    const int* im  = in_map  + k * M_PAIRS + tile;
    const int* om  = out_map + k * M_PAIRS + tile;

    // ---- Stage: 128 rows x 8 quads, coalesced; 8 float4 per thread.
    #pragma unroll
    for (int i = 0; i < (PAIRS_PER_BLOCK * (C / 4)) / THREADS; i++) {
        int q  = threadIdx.x + i * THREADS;
        int pr = q >> 3;
        int qq = q & 7;
        int irow = __ldg(im + pr);
        ((float4*)&srow[pr][0])[qq] =
            __ldg((const float4*)(input + (size_t)irow * C) + qq);
    }

    // ---- Weights, input-pair packed:
    //   wA[i] = (W[2i][c0], W[2i+1][c0]),  wB[i] = (W[2i][c1], W[2i+1][c1])
    const float* Wk = kernel + k * C * C;
    unsigned long long wA[C / 2], wB[C / 2];
    #pragma unroll
    for (int i = 0; i < C / 2; i++) {
        float2 f = __ldg((const float2*)(Wk + (2 * i)     * C) + chalf);
        float2 g = __ldg((const float2*)(Wk + (2 * i + 1) * C) + chalf);
        asm("mov.b64 %0, {%1, %2};" : "=l"(wA[i]) : "f"(f.x), "f"(g.x));
        asm("mov.b64 %0, {%1, %2};" : "=l"(wB[i]) : "f"(f.y), "f"(g.y));
    }

    __syncthreads();

    const int pbase = warp * PAIRS_PER_WARP;

    #pragma unroll 4
    for (int t = 0; t < STEPS; t++) {
        const int pw = 2 * t + half;            // pair index within warp

        const ulonglong2* r2 = (const ulonglong2*)&srow[pbase + pw][0];

        unsigned long long accA = 0ULL, accB = 0ULL;   // packed (even, odd) partials
        #pragma unroll
        for (int j = 0; j < C / 4; j++) {
            ulonglong2 a = r2[j];               // LDS.128, 2 distinct rows/warp
            asm("fma.rn.f32x2 %0, %1, %2, %0;" : "+l"(accA) : "l"(a.x), "l"(wA[2 * j]));
            asm("fma.rn.f32x2 %0, %1, %2, %0;" : "+l"(accA) : "l"(a.y), "l"(wA[2 * j + 1]));
            asm("fma.rn.f32x2 %0, %1, %2, %0;" : "+l"(accB) : "l"(a.x), "l"(wB[2 * j]));
            asm("fma.rn.f32x2 %0, %1, %2, %0;" : "+l"(accB) : "l"(a.y), "l"(wB[2 * j + 1]));
        }
        float a0, a1, b0, b1;
        asm("mov.b64 {%0, %1}, %2;" : "=f"(a0), "=f"(a1) : "l"(accA));
        asm("mov.b64 {%0, %1}, %2;" : "=f"(b0), "=f"(b1) : "l"(accB));

        // (c0, c1) -> per-warp result buffer (8B per lane, contiguous per pair)
        float2* dst = (float2*)&sres[warp][pw][2 * chalf];
        *dst = make_float2(a0 + a1, b0 + b1);
    }

    __syncwarp();
    // Make generic-proxy STS results visible to the async (TMA) proxy.
    asm volatile("fence.proxy.async.shared::cta;" ::: "memory");

    // ---- Scatter: lanes 0-3 each issue 8 x 128B bulk reductions.
    if (lane < 4) {
        #pragma unroll
        for (int i = 0; i < 8; i++) {
            const int pw   = lane * 8 + i;
            const int orow = __ldg(om + pbase + pw);
            float* gdst = out + (size_t)orow * C;
            uint32_t src = smem_u32(&sres[warp][pw][0]);
            asm volatile(
                "cp.reduce.async.bulk.global.shared::cta.bulk_group.add.f32 "
                "[%0], [%1], 128;"
                :: "l"(gdst), "r"(src) : "memory");
        }
        asm volatile("cp.async.bulk.commit_group;" ::: "memory");
        asm volatile("cp.async.bulk.wait_group 0;" ::: "memory");
    }
}

// ---------------------------------------------------------------------------
// Launch
// ---------------------------------------------------------------------------
extern "C" void kernel_launch(void* const* d_in, const int* in_sizes, int n_in,
                              void* d_out, int out_size)
{
    const float* input   = (const float*)d_in[0];
    const float* kernelw = (const float*)d_in[1];
    const float* bias    = (const float*)d_in[2];
    const int*   in_map  = (const int*)  d_in[3];
    const int*   out_map = (const int*)  d_in[4];
    float*       out     = (float*)d_out;

    const int total4 = N_VOX * (C / 4);
    bias_init_kernel<<<(total4 + 255) / 256, 256>>>(out, bias);

    dim3 grid(M_PAIRS / PAIRS_PER_BLOCK, K_OFF);
    scatter_gemm_kernel<<<grid, THREADS>>>(input, kernelw, in_map, out_map, out);
}

// round 12
// speedup vs baseline: 1.1978x; 1.1102x over previous
#include <cuda_runtime.h>
#include <cstdint>

#define N_VOX   262144
#define M_PAIRS 131072
#define K_OFF   27
#define C       32
#define CPAD    36        // row stride in floats (144B; 16B-aligned, bank-shifted)

// ---------------------------------------------------------------------------
// Kernel 1: out[n][c] = bias[c]  (bias add commutes with the scatter-adds)
// ---------------------------------------------------------------------------
__global__ void bias_init_kernel(float* __restrict__ out,
                                 const float* __restrict__ bias)
{
    int t = blockIdx.x * blockDim.x + threadIdx.x;
    const int total4 = N_VOX * (C / 4);
    if (t < total4) {
        const float4* b4 = (const float4*)bias;
        float4* o4 = (float4*)out;
        o4[t] = b4[t & 7];
    }
}

// ---------------------------------------------------------------------------
// Kernel 2: TMA bulk gather -> smem -> input-packed f32x2 GEMM (R9 scheme)
//           -> red.v2 scatter.
//
//   Gather: each thread issues one cp.async.bulk (128B row, random global
//   address) into its pair's padded smem row; completion via one mbarrier
//   with expect_tx = 16 KB. Gather bytes ride the TMA pipe, NOT L1tex.
//   Compute (R9, best known): 16-lane half owns one pair; lane covers
//   channels (2c, 2c+1); row read as ulonglong2 (LDS.128 -> packed f32x2
//   input pairs) consumed directly by fma.rn.f32x2.
//   Scatter: red.global.add.v2.f32 (contiguous 128B per pair).
// ---------------------------------------------------------------------------
#define THREADS          128
#define WARPS_PER_BLOCK  4
#define PAIRS_PER_BLOCK  128
#define PAIRS_PER_WARP   32
#define STEPS            16            // 2 pairs per step (one per half-warp)

__device__ __forceinline__ uint32_t smem_u32(const void* p) {
    uint32_t a;
    asm("{ .reg .u64 t; cvta.to.shared.u64 t, %1; cvt.u32.u64 %0, t; }"
        : "=r"(a) : "l"(p));
    return a;
}

__global__ __launch_bounds__(THREADS)
void scatter_gemm_kernel(const float* __restrict__ input,
                         const float* __restrict__ kernel,
                         const int*   __restrict__ in_map,
                         const int*   __restrict__ out_map,
                         float*       __restrict__ out)
{
    __shared__ float srow[PAIRS_PER_BLOCK][CPAD];    // 18 KB staged rows
    __shared__ alignas(8) unsigned long long mbar;   // gather completion barrier

    const int k     = blockIdx.y;
    const int lane  = threadIdx.x & 31;
    const int warp  = threadIdx.x >> 5;
    const int half  = lane >> 4;          // which pair of the step
    const int chalf = lane & 15;          // covers channels 2*chalf, 2*chalf+1

    const int tile = blockIdx.x * PAIRS_PER_BLOCK;
    const int* im  = in_map  + k * M_PAIRS + tile;
    const int* om  = out_map + k * M_PAIRS + tile;

    const uint32_t mbar_a = smem_u32(&mbar);

    // ---- Barrier init + expected bytes (single thread), then publish.
    if (threadIdx.x == 0) {
        asm volatile("mbarrier.init.shared.b64 [%0], 1;" :: "r"(mbar_a) : "memory");
        asm volatile("mbarrier.arrive.expect_tx.shared.b64 _, [%0], %1;"
                     :: "r"(mbar_a), "r"(PAIRS_PER_BLOCK * C * 4) : "memory");
    }
    __syncthreads();

    // ---- Gather: one 128B bulk copy per thread (row -> padded smem slot).
    {
        const int irow = __ldg(im + threadIdx.x);
        const float* src = input + (size_t)irow * C;
        const uint32_t dst = smem_u32(&srow[threadIdx.x][0]);
        asm volatile(
            "cp.async.bulk.shared::cta.global.mbarrier::complete_tx::bytes "
            "[%0], [%1], %2, [%3];"
            :: "r"(dst), "l"(src), "r"(C * 4), "r"(mbar_a) : "memory");
    }

    // ---- Weights (overlap with gather), input-pair packed:
    //   wA[i] = (W[2i][c0], W[2i+1][c0]),  wB[i] = (W[2i][c1], W[2i+1][c1])
    const float* Wk = kernel + k * C * C;
    unsigned long long wA[C / 2], wB[C / 2];
    #pragma unroll
    for (int i = 0; i < C / 2; i++) {
        float2 f = __ldg((const float2*)(Wk + (2 * i)     * C) + chalf);
        float2 g = __ldg((const float2*)(Wk + (2 * i + 1) * C) + chalf);
        asm("mov.b64 %0, {%1, %2};" : "=l"(wA[i]) : "f"(f.x), "f"(g.x));
        asm("mov.b64 %0, {%1, %2};" : "=l"(wB[i]) : "f"(f.y), "f"(g.y));
    }

    // ---- Wait for all 16 KB of gathered rows (acquire orders the LDS below).
    {
        uint32_t done;
        asm volatile(
            "{\n\t"
            ".reg .pred p;\n\t"
            "mbarrier.try_wait.parity.acquire.cta.shared::cta.b64 p, [%1], 0;\n\t"
            "selp.b32 %0, 1, 0, p;\n\t"
            "}"
            : "=r"(done) : "r"(mbar_a) : "memory");
        if (!done) {
            asm volatile(
                "{\n\t"
                ".reg .pred P1;\n\t"
                "WAIT_LOOP_%=:\n\t"
                "mbarrier.try_wait.parity.acquire.cta.shared::cta.b64 P1, [%0], 0, 0x989680;\n\t"
                "@P1 bra.uni WAIT_DONE_%=;\n\t"
                "bra.uni WAIT_LOOP_%=;\n\t"
                "WAIT_DONE_%=:\n\t"
                "}"
                :: "r"(mbar_a) : "memory");
        }
    }

    const int pbase = warp * PAIRS_PER_WARP;

    #pragma unroll 4
    for (int t = 0; t < STEPS; t++) {
        const int pw   = 2 * t + half;          // pair index within warp
        const int orow = __ldg(om + pbase + pw);

        const ulonglong2* r2 = (const ulonglong2*)&srow[pbase + pw][0];

        unsigned long long accA = 0ULL, accB = 0ULL;   // packed (even, odd) partials
        #pragma unroll
        for (int j = 0; j < C / 4; j++) {
            ulonglong2 a = r2[j];               // LDS.128, 2 distinct rows/warp
            asm("fma.rn.f32x2 %0, %1, %2, %0;" : "+l"(accA) : "l"(a.x), "l"(wA[2 * j]));
            asm("fma.rn.f32x2 %0, %1, %2, %0;" : "+l"(accA) : "l"(a.y), "l"(wA[2 * j + 1]));
            asm("fma.rn.f32x2 %0, %1, %2, %0;" : "+l"(accB) : "l"(a.x), "l"(wB[2 * j]));
            asm("fma.rn.f32x2 %0, %1, %2, %0;" : "+l"(accB) : "l"(a.y), "l"(wB[2 * j + 1]));
        }
        float a0, a1, b0, b1;
        asm("mov.b64 {%0, %1}, %2;" : "=f"(a0), "=f"(a1) : "l"(accA));
        asm("mov.b64 {%0, %1}, %2;" : "=f"(b0), "=f"(b1) : "l"(accB));
        const float c0 = a0 + a1;
        const float c1 = b0 + b1;

        float* dst = out + (size_t)orow * C + 2 * chalf;   // 8B aligned
        asm volatile("red.global.add.v2.f32 [%0], {%1, %2};"
                     :: "l"(dst), "f"(c0), "f"(c1) : "memory");
    }
}

// ---------------------------------------------------------------------------
// Launch
// ---------------------------------------------------------------------------
extern "C" void kernel_launch(void* const* d_in, const int* in_sizes, int n_in,
                              void* d_out, int out_size)
{
    const float* input   = (const float*)d_in[0];
    const float* kernelw = (const float*)d_in[1];
    const float* bias    = (const float*)d_in[2];
    const int*   in_map  = (const int*)  d_in[3];
    const int*   out_map = (const int*)  d_in[4];
    float*       out     = (float*)d_out;

    const int total4 = N_VOX * (C / 4);
    bias_init_kernel<<<(total4 + 255) / 256, 256>>>(out, bias);

    dim3 grid(M_PAIRS / PAIRS_PER_BLOCK, K_OFF);
    scatter_gemm_kernel<<<grid, THREADS>>>(input, kernelw, in_map, out_map, out);
}